// round 1
// baseline (speedup 1.0000x reference)
#include <cuda_runtime.h>
#include <float.h>
#include <stdint.h>

#define D2 64
#define MAX_TABLE_LEN 8192

// Scratch (no allocation allowed in kernel_launch)
__device__ __align__(16) float g_tx2[MAX_TABLE_LEN * D2];
__device__ __align__(16) float g_ty2[MAX_TABLE_LEN * D2];
__device__ float g_max2[2];

// ---------------------------------------------------------------------------
// Float atomic max that handles mixed signs correctly.
// positive floats: signed-int ordering == float ordering -> atomicMax(int)
// negative floats: unsigned ordering reversed           -> atomicMin(uint)
// Cross-sign cases also resolve correctly under this scheme.
// ---------------------------------------------------------------------------
__device__ __forceinline__ void atomicMaxFloat(float* addr, float val) {
    if (val >= 0.0f) {
        atomicMax((int*)addr, __float_as_int(val));
    } else {
        atomicMin((unsigned int*)addr, __float_as_uint(val));
    }
}

__global__ void init_kernel() {
    g_max2[0] = -FLT_MAX;
    g_max2[1] = -FLT_MAX;
}

// Fused global max over both tables. n4 = element count / 4.
__global__ void max_kernel(const float4* __restrict__ x,
                           const float4* __restrict__ y, int n4) {
    float mx = -FLT_MAX, my = -FLT_MAX;
    for (int i = blockIdx.x * blockDim.x + threadIdx.x; i < n4;
         i += gridDim.x * blockDim.x) {
        float4 a = x[i];
        mx = fmaxf(mx, fmaxf(fmaxf(a.x, a.y), fmaxf(a.z, a.w)));
        float4 b = y[i];
        my = fmaxf(my, fmaxf(fmaxf(b.x, b.y), fmaxf(b.z, b.w)));
    }
#pragma unroll
    for (int o = 16; o > 0; o >>= 1) {
        mx = fmaxf(mx, __shfl_xor_sync(0xFFFFFFFFu, mx, o));
        my = fmaxf(my, __shfl_xor_sync(0xFFFFFFFFu, my, o));
    }
    __shared__ float smx[8], smy[8];
    int w = threadIdx.x >> 5, l = threadIdx.x & 31;
    if (l == 0) { smx[w] = mx; smy[w] = my; }
    __syncthreads();
    if (threadIdx.x == 0) {
        int nw = blockDim.x >> 5;
        for (int i = 1; i < nw; i++) {
            mx = fmaxf(mx, smx[i]);
            my = fmaxf(my, smy[i]);
        }
        atomicMaxFloat(&g_max2[0], mx);
        atomicMaxFloat(&g_max2[1], my);
    }
}

// Build pair-reduced tables:
//   TX2[i][j] = (x[i][2j] + x[i][2j+1]) * (0.1/max_x) + (F[i][2j] + F[i][2j+1])
// Flat pair index t maps to float2 at element 2t -> fully linear access.
// One thread = one float4 input chunk = 2 output pairs (float2 out).
__global__ void build_kernel(const float4* __restrict__ x,
                             const float4* __restrict__ y,
                             const float4* __restrict__ f, int n4) {
    int i = blockIdx.x * blockDim.x + threadIdx.x;
    if (i >= n4) return;
    float invx = 0.1f / g_max2[0];
    float invy = 0.1f / g_max2[1];
    float4 a = f[i];
    float fs0 = a.x + a.y;
    float fs1 = a.z + a.w;
    float4 xv = x[i];
    float4 yv = y[i];
    float2 tx, ty;
    tx.x = (xv.x + xv.y) * invx + fs0;
    tx.y = (xv.z + xv.w) * invx + fs1;
    ty.x = (yv.x + yv.y) * invy + fs0;
    ty.y = (yv.z + yv.w) * invy + fs1;
    ((float2*)g_tx2)[i] = tx;
    ((float2*)g_ty2)[i] = ty;
}

// Gather: one warp per output row (262144 rows x 128 floats).
// Output row = [TX2[i0][0..63], TY2[i1][0..63]].
// lanes 0-15 read TX2 float4s, lanes 16-31 read TY2 float4s.
// Write: 32 consecutive float4 = 512B fully coalesced.
__global__ void __launch_bounds__(256)
gather_kernel(const int2* __restrict__ pos, float4* __restrict__ out,
              int nrows) {
    int warp = (blockIdx.x * blockDim.x + threadIdx.x) >> 5;
    int lane = threadIdx.x & 31;
    if (warp >= nrows) return;
    int2 p = __ldg(&pos[warp]);
    int i0 = (p.x < 0) ? 1 : p.x;
    int i1 = (p.y < 0) ? 1 : p.y;
    float4 v;
    if (lane < 16) {
        v = __ldg((const float4*)g_tx2 + (size_t)i0 * 16 + lane);
    } else {
        v = __ldg((const float4*)g_ty2 + (size_t)i1 * 16 + (lane - 16));
    }
    out[(size_t)warp * 32 + lane] = v;
}

extern "C" void kernel_launch(void* const* d_in, const int* in_sizes, int n_in,
                              void* d_out, int out_size) {
    const int*   positions   = (const int*)d_in[0];   // [16,512,32,2] int32
    const float* fixed_table = (const float*)d_in[1]; // [table_len,128]
    const float* table_x     = (const float*)d_in[2];
    const float* table_y     = (const float*)d_in[3];

    int table_elems = in_sizes[1];        // table_len * 128
    int n4_tab      = table_elems / 4;    // float4 count per table
    int nrows       = in_sizes[0] / 2;    // 262144 output rows

    init_kernel<<<1, 1>>>();
    max_kernel<<<256, 256>>>((const float4*)table_x, (const float4*)table_y,
                             n4_tab);
    {
        int n4 = table_elems / 4;  // one thread per float4 = 2 pairs
        int threads = 256;
        int blocks = (n4 + threads - 1) / threads;
        build_kernel<<<blocks, threads>>>((const float4*)table_x,
                                          (const float4*)table_y,
                                          (const float4*)fixed_table, n4);
    }
    {
        int threads = 256;  // 8 warps per block, 1 warp per row
        int total_threads = nrows * 32;
        int blocks = (total_threads + threads - 1) / threads;
        gather_kernel<<<blocks, threads>>>((const int2*)positions,
                                           (float4*)d_out, nrows);
    }
}

// round 2
// speedup vs baseline: 1.2780x; 1.2780x over previous
#include <cuda_runtime.h>
#include <float.h>
#include <stdint.h>

#define D2 64
#define MAX_TABLE_LEN 8192
#define MAXB 132

// Scratch (no allocation allowed in kernel_launch)
__device__ __align__(16) float g_tx2[MAX_TABLE_LEN * D2];
__device__ __align__(16) float g_ty2[MAX_TABLE_LEN * D2];
__device__ float g_pmx[MAXB];
__device__ float g_pmy[MAXB];

// ---------------------------------------------------------------------------
// Pass 1: per-block partial max of both tables. Every block writes its slot
// unconditionally -> no reset/init kernel, no atomics.
// ---------------------------------------------------------------------------
__global__ void __launch_bounds__(256)
max_kernel(const float4* __restrict__ x, const float4* __restrict__ y, int n4) {
    float mx = -FLT_MAX, my = -FLT_MAX;
    for (int i = blockIdx.x * blockDim.x + threadIdx.x; i < n4;
         i += gridDim.x * blockDim.x) {
        float4 a = x[i];
        mx = fmaxf(mx, fmaxf(fmaxf(a.x, a.y), fmaxf(a.z, a.w)));
        float4 b = y[i];
        my = fmaxf(my, fmaxf(fmaxf(b.x, b.y), fmaxf(b.z, b.w)));
    }
#pragma unroll
    for (int o = 16; o > 0; o >>= 1) {
        mx = fmaxf(mx, __shfl_xor_sync(0xFFFFFFFFu, mx, o));
        my = fmaxf(my, __shfl_xor_sync(0xFFFFFFFFu, my, o));
    }
    __shared__ float smx[8], smy[8];
    int w = threadIdx.x >> 5, l = threadIdx.x & 31;
    if (l == 0) { smx[w] = mx; smy[w] = my; }
    __syncthreads();
    if (threadIdx.x == 0) {
        int nw = blockDim.x >> 5;
        for (int i = 1; i < nw; i++) {
            mx = fmaxf(mx, smx[i]);
            my = fmaxf(my, smy[i]);
        }
        g_pmx[blockIdx.x] = mx;
        g_pmy[blockIdx.x] = my;
    }
}

// ---------------------------------------------------------------------------
// Pass 2: build pair-reduced tables
//   TX2[i][j] = (x[i][2j]+x[i][2j+1]) * (0.1/max_x) + (F[i][2j]+F[i][2j+1])
// Each block first reduces the 132 partial maxes (warp 0, L2 broadcast hits).
// One thread = one float4 input chunk = 2 output pairs (float2 out).
// ---------------------------------------------------------------------------
__global__ void __launch_bounds__(256)
build_kernel(const float4* __restrict__ x, const float4* __restrict__ y,
             const float4* __restrict__ f, int n4) {
    __shared__ float s_invx, s_invy;
    if (threadIdx.x < 32) {
        float mx = -FLT_MAX, my = -FLT_MAX;
        for (int i = threadIdx.x; i < MAXB; i += 32) {
            mx = fmaxf(mx, g_pmx[i]);
            my = fmaxf(my, g_pmy[i]);
        }
#pragma unroll
        for (int o = 16; o > 0; o >>= 1) {
            mx = fmaxf(mx, __shfl_xor_sync(0xFFFFFFFFu, mx, o));
            my = fmaxf(my, __shfl_xor_sync(0xFFFFFFFFu, my, o));
        }
        if (threadIdx.x == 0) {
            s_invx = 0.1f / mx;
            s_invy = 0.1f / my;
        }
    }
    __syncthreads();

    int i = blockIdx.x * blockDim.x + threadIdx.x;
    if (i >= n4) return;
    float invx = s_invx, invy = s_invy;
    float4 a = f[i];
    float fs0 = a.x + a.y;
    float fs1 = a.z + a.w;
    float4 xv = x[i];
    float4 yv = y[i];
    float2 tx, ty;
    tx.x = (xv.x + xv.y) * invx + fs0;
    tx.y = (xv.z + xv.w) * invx + fs1;
    ty.x = (yv.x + yv.y) * invy + fs0;
    ty.y = (yv.z + yv.w) * invy + fs1;
    ((float2*)g_tx2)[i] = tx;
    ((float2*)g_ty2)[i] = ty;
}

// ---------------------------------------------------------------------------
// Pass 3: gather. 4 rows per warp, loads front-batched for MLP=4/thread.
// Row layout: out row = [TX2[i0][0..63], TY2[i1][0..63]] = 32 float4.
// lanes 0-15 take the TX2 half, lanes 16-31 the TY2 half.
// Each warp writes 4 x 512B fully-coalesced blocks.
// ---------------------------------------------------------------------------
#define ROWS_PER_WARP 4

__global__ void __launch_bounds__(256)
gather_kernel(const int2* __restrict__ pos, float4* __restrict__ out,
              int nrows) {
    int warp = (blockIdx.x * blockDim.x + threadIdx.x) >> 5;
    int lane = threadIdx.x & 31;
    int base = warp * ROWS_PER_WARP;
    if (base >= nrows) return;

    const float4* tab = (lane < 16) ? (const float4*)g_tx2
                                    : (const float4*)g_ty2;
    int off = lane & 15;
    bool use_x = (lane < 16);

    // Front-batch: all pos loads, then all independent table gathers.
    int idx[ROWS_PER_WARP];
#pragma unroll
    for (int k = 0; k < ROWS_PER_WARP; k++) {
        int r = base + k;
        int2 p = (r < nrows) ? __ldg(&pos[r]) : make_int2(1, 1);
        int t = use_x ? p.x : p.y;
        idx[k] = (t < 0) ? 1 : t;
    }

    float4 v[ROWS_PER_WARP];
#pragma unroll
    for (int k = 0; k < ROWS_PER_WARP; k++) {
        v[k] = __ldg(tab + (size_t)idx[k] * 16 + off);
    }

#pragma unroll
    for (int k = 0; k < ROWS_PER_WARP; k++) {
        int r = base + k;
        if (r < nrows) out[(size_t)r * 32 + lane] = v[k];
    }
}

extern "C" void kernel_launch(void* const* d_in, const int* in_sizes, int n_in,
                              void* d_out, int out_size) {
    const int*   positions   = (const int*)d_in[0];   // [16,512,32,2] int32
    const float* fixed_table = (const float*)d_in[1]; // [table_len,128]
    const float* table_x     = (const float*)d_in[2];
    const float* table_y     = (const float*)d_in[3];

    int table_elems = in_sizes[1];        // table_len * 128
    int n4_tab      = table_elems / 4;    // float4 count per table
    int nrows       = in_sizes[0] / 2;    // 262144 output rows

    max_kernel<<<MAXB, 256>>>((const float4*)table_x, (const float4*)table_y,
                              n4_tab);
    {
        int threads = 256;
        int blocks = (n4_tab + threads - 1) / threads;
        build_kernel<<<blocks, threads>>>((const float4*)table_x,
                                          (const float4*)table_y,
                                          (const float4*)fixed_table, n4_tab);
    }
    {
        int threads = 256;  // 8 warps/block, 4 rows/warp
        int nwarps = (nrows + ROWS_PER_WARP - 1) / ROWS_PER_WARP;
        int blocks = (nwarps * 32 + threads - 1) / threads;
        gather_kernel<<<blocks, threads>>>((const int2*)positions,
                                           (float4*)d_out, nrows);
    }
}

// round 4
// speedup vs baseline: 1.3385x; 1.0473x over previous
#include <cuda_runtime.h>
#include <float.h>
#include <stdint.h>

#define D2 64
#define MAX_TABLE_LEN 8192
#define MAXB 512

// Scratch (no allocation allowed in kernel_launch)
__device__ __align__(16) float g_tx2[MAX_TABLE_LEN * D2];
__device__ __align__(16) float g_ty2[MAX_TABLE_LEN * D2];
__device__ float g_pmx[MAXB];
__device__ float g_pmy[MAXB];

// ---------------------------------------------------------------------------
// Pass 1: per-block partial max of both tables. 512 blocks -> whole scan in
// flight at once (one float4 per table per thread at n4~131K). Every block
// writes its slot unconditionally -> no reset kernel, no atomics.
// ---------------------------------------------------------------------------
__global__ void __launch_bounds__(256)
max_kernel(const float4* __restrict__ x, const float4* __restrict__ y, int n4) {
    float mx = -FLT_MAX, my = -FLT_MAX;
    for (int i = blockIdx.x * blockDim.x + threadIdx.x; i < n4;
         i += gridDim.x * blockDim.x) {
        float4 a = x[i];
        float4 b = y[i];
        mx = fmaxf(mx, fmaxf(fmaxf(a.x, a.y), fmaxf(a.z, a.w)));
        my = fmaxf(my, fmaxf(fmaxf(b.x, b.y), fmaxf(b.z, b.w)));
    }
#pragma unroll
    for (int o = 16; o > 0; o >>= 1) {
        mx = fmaxf(mx, __shfl_xor_sync(0xFFFFFFFFu, mx, o));
        my = fmaxf(my, __shfl_xor_sync(0xFFFFFFFFu, my, o));
    }
    __shared__ float smx[8], smy[8];
    int w = threadIdx.x >> 5, l = threadIdx.x & 31;
    if (l == 0) { smx[w] = mx; smy[w] = my; }
    __syncthreads();
    if (threadIdx.x == 0) {
        int nw = blockDim.x >> 5;
        for (int i = 1; i < nw; i++) {
            mx = fmaxf(mx, smx[i]);
            my = fmaxf(my, smy[i]);
        }
        g_pmx[blockIdx.x] = mx;
        g_pmy[blockIdx.x] = my;
    }
}

// ---------------------------------------------------------------------------
// Pass 2: build pair-reduced tables
//   TX2[i][j] = (x[i][2j]+x[i][2j+1]) * (0.1/max_x) + (F[i][2j]+F[i][2j+1])
// Each block first reduces the 512 partial maxes (warp 0, L2 broadcast).
// One thread = one float4 input chunk = 2 output pairs (float2 out).
// x/y re-reads are L2-hot from pass 1.
// ---------------------------------------------------------------------------
__global__ void __launch_bounds__(256)
build_kernel(const float4* __restrict__ x, const float4* __restrict__ y,
             const float4* __restrict__ f, int n4) {
    __shared__ float s_invx, s_invy;
    if (threadIdx.x < 32) {
        float mx = -FLT_MAX, my = -FLT_MAX;
        for (int i = threadIdx.x; i < MAXB; i += 32) {
            mx = fmaxf(mx, g_pmx[i]);
            my = fmaxf(my, g_pmy[i]);
        }
#pragma unroll
        for (int o = 16; o > 0; o >>= 1) {
            mx = fmaxf(mx, __shfl_xor_sync(0xFFFFFFFFu, mx, o));
            my = fmaxf(my, __shfl_xor_sync(0xFFFFFFFFu, my, o));
        }
        if (threadIdx.x == 0) {
            s_invx = 0.1f / mx;
            s_invy = 0.1f / my;
        }
    }
    __syncthreads();

    int i = blockIdx.x * blockDim.x + threadIdx.x;
    if (i >= n4) return;
    float invx = s_invx, invy = s_invy;
    float4 a = f[i];
    float fs0 = a.x + a.y;
    float fs1 = a.z + a.w;
    float4 xv = x[i];
    float4 yv = y[i];
    float2 tx, ty;
    tx.x = (xv.x + xv.y) * invx + fs0;
    tx.y = (xv.z + xv.w) * invx + fs1;
    ty.x = (yv.x + yv.y) * invy + fs0;
    ty.y = (yv.z + yv.w) * invy + fs1;
    ((float2*)g_tx2)[i] = tx;
    ((float2*)g_ty2)[i] = ty;
}

// ---------------------------------------------------------------------------
// Pass 3: gather. 8 rows per warp, loads front-batched for MLP=8/thread.
// Row layout: out row = [TX2[i0][0..63], TY2[i1][0..63]] = 32 float4.
// lanes 0-15 take the TX2 half, lanes 16-31 the TY2 half.
// Streaming stores (__stcs): output is never re-read, keep tables L2-hot.
// ---------------------------------------------------------------------------
#define ROWS_PER_WARP 8

__global__ void __launch_bounds__(256)
gather_kernel(const int2* __restrict__ pos, float4* __restrict__ out,
              int nrows) {
    int warp = (blockIdx.x * blockDim.x + threadIdx.x) >> 5;
    int lane = threadIdx.x & 31;
    int base = warp * ROWS_PER_WARP;
    if (base >= nrows) return;

    const float4* tab = (lane < 16) ? (const float4*)g_tx2
                                    : (const float4*)g_ty2;
    int off = lane & 15;
    bool use_x = (lane < 16);

    // Front-batch: all pos loads, then all independent table gathers.
    int idx[ROWS_PER_WARP];
#pragma unroll
    for (int k = 0; k < ROWS_PER_WARP; k++) {
        int r = base + k;
        int2 p = (r < nrows) ? __ldg(&pos[r]) : make_int2(1, 1);
        int t = use_x ? p.x : p.y;
        idx[k] = (t < 0) ? 1 : t;
    }

    float4 v[ROWS_PER_WARP];
#pragma unroll
    for (int k = 0; k < ROWS_PER_WARP; k++) {
        v[k] = __ldg(tab + (size_t)idx[k] * 16 + off);
    }

#pragma unroll
    for (int k = 0; k < ROWS_PER_WARP; k++) {
        int r = base + k;
        if (r < nrows) __stcs(&out[(size_t)r * 32 + lane], v[k]);
    }
}

extern "C" void kernel_launch(void* const* d_in, const int* in_sizes, int n_in,
                              void* d_out, int out_size) {
    const int*   positions   = (const int*)d_in[0];   // [16,512,32,2] int32
    const float* fixed_table = (const float*)d_in[1]; // [table_len,128]
    const float* table_x     = (const float*)d_in[2];
    const float* table_y     = (const float*)d_in[3];

    int table_elems = in_sizes[1];        // table_len * 128
    int n4_tab      = table_elems / 4;    // float4 count per table
    int nrows       = in_sizes[0] / 2;    // 262144 output rows

    max_kernel<<<MAXB, 256>>>((const float4*)table_x, (const float4*)table_y,
                              n4_tab);
    {
        int threads = 256;
        int blocks = (n4_tab + threads - 1) / threads;
        build_kernel<<<blocks, threads>>>((const float4*)table_x,
                                          (const float4*)table_y,
                                          (const float4*)fixed_table, n4_tab);
    }
    {
        int threads = 256;  // 8 warps/block, 8 rows/warp
        int nwarps = (nrows + ROWS_PER_WARP - 1) / ROWS_PER_WARP;
        int blocks = (nwarps * 32 + threads - 1) / threads;
        gather_kernel<<<blocks, threads>>>((const int2*)positions,
                                           (float4*)d_out, nrows);
    }
}

// round 7
// speedup vs baseline: 1.4365x; 1.0732x over previous
#include <cuda_runtime.h>
#include <float.h>
#include <stdint.h>

#define D2 64
#define MAX_TABLE_LEN 8192
#define MAXB_MAX 132
#define MAXB_BUILD 264
#define ROWS_PER_WARP 8

// Scratch (no allocation allowed in kernel_launch)
__device__ __align__(16) float g_tx2[MAX_TABLE_LEN * D2];
__device__ __align__(16) float g_ty2[MAX_TABLE_LEN * D2];
__device__ float g_pmx[MAXB_MAX];
__device__ float g_pmy[MAXB_MAX];
__device__ float g_inv2[2];
__device__ unsigned int g_done = 0;  // fence-counter; last block resets to 0

// ---------------------------------------------------------------------------
// Pass 1: global max of both tables.
// 132 blocks x 256 thr; each thread front-batches 4 predicated float4 loads
// per table (8 independent LDGs in flight -> one DRAM round-trip total).
// The LAST block to finish (fence-counter) reduces the 132 partials and
// writes 0.1/max directly -> no separate reduce, no spin, no deadlock risk.
// ---------------------------------------------------------------------------
__global__ void __launch_bounds__(256)
max_kernel(const float4* __restrict__ x, const float4* __restrict__ y, int n4) {
    const int tid = threadIdx.x;
    const int stride = MAXB_MAX * 256;
    int gtid = blockIdx.x * 256 + tid;

    float mx = -FLT_MAX, my = -FLT_MAX;
    // 4-way batched, predicated: all loads issued before any max chain binds.
    int base = gtid;
    while (base < n4) {
        float4 a[4], b[4];
#pragma unroll
        for (int k = 0; k < 4; k++) {
            int i = base + k * stride;
            bool ok = (i < n4);
            a[k] = ok ? x[i] : make_float4(-FLT_MAX, -FLT_MAX, -FLT_MAX, -FLT_MAX);
            b[k] = ok ? y[i] : make_float4(-FLT_MAX, -FLT_MAX, -FLT_MAX, -FLT_MAX);
        }
#pragma unroll
        for (int k = 0; k < 4; k++) {
            mx = fmaxf(mx, fmaxf(fmaxf(a[k].x, a[k].y), fmaxf(a[k].z, a[k].w)));
            my = fmaxf(my, fmaxf(fmaxf(b[k].x, b[k].y), fmaxf(b[k].z, b[k].w)));
        }
        base += 4 * stride;
    }

#pragma unroll
    for (int o = 16; o > 0; o >>= 1) {
        mx = fmaxf(mx, __shfl_xor_sync(0xFFFFFFFFu, mx, o));
        my = fmaxf(my, __shfl_xor_sync(0xFFFFFFFFu, my, o));
    }
    __shared__ float smx[8], smy[8];
    __shared__ bool s_last;
    int w = tid >> 5, l = tid & 31;
    if (l == 0) { smx[w] = mx; smy[w] = my; }
    __syncthreads();
    if (tid == 0) {
        for (int i = 1; i < 8; i++) {
            mx = fmaxf(mx, smx[i]);
            my = fmaxf(my, smy[i]);
        }
        g_pmx[blockIdx.x] = mx;
        g_pmy[blockIdx.x] = my;
        __threadfence();
        unsigned int prev = atomicAdd(&g_done, 1u);
        s_last = (prev == MAXB_MAX - 1);
    }
    __syncthreads();

    // Last-finishing block: final reduction of partials (warp 0 only).
    if (s_last && tid < 32) {
        float fx = -FLT_MAX, fy = -FLT_MAX;
        for (int i = tid; i < MAXB_MAX; i += 32) {
            fx = fmaxf(fx, g_pmx[i]);
            fy = fmaxf(fy, g_pmy[i]);
        }
#pragma unroll
        for (int o = 16; o > 0; o >>= 1) {
            fx = fmaxf(fx, __shfl_xor_sync(0xFFFFFFFFu, fx, o));
            fy = fmaxf(fy, __shfl_xor_sync(0xFFFFFFFFu, fy, o));
        }
        if (tid == 0) {
            g_inv2[0] = 0.1f / fx;
            g_inv2[1] = 0.1f / fy;
            g_done = 0;  // reset for next launch (graph replay determinism)
        }
    }
}

// ---------------------------------------------------------------------------
// Pass 2: build pair-reduced tables
//   TX2[i][j] = (x[i][2j]+x[i][2j+1]) * (0.1/max_x) + (F[i][2j]+F[i][2j+1])
// 264 blocks x 256 thr, 2-way batched (6 loads in flight per thread).
// invx/invy read via broadcast load (written by max_kernel's last block;
// kernel boundary orders it). x/y are L2-hot from pass 1.
// ---------------------------------------------------------------------------
__global__ void __launch_bounds__(256)
build_kernel(const float4* __restrict__ x, const float4* __restrict__ y,
             const float4* __restrict__ f, int n4) {
    const float invx = g_inv2[0];
    const float invy = g_inv2[1];
    const int stride = MAXB_BUILD * 256;
    int base = blockIdx.x * 256 + threadIdx.x;

    while (base < n4) {
        float4 fa[2], xa[2], ya[2];
        int i1 = base + stride;
        bool ok1 = (i1 < n4);
        fa[0] = f[base];
        xa[0] = x[base];
        ya[0] = y[base];
        if (ok1) {
            fa[1] = f[i1];
            xa[1] = x[i1];
            ya[1] = y[i1];
        }
#pragma unroll
        for (int k = 0; k < 2; k++) {
            int i = base + k * stride;
            if (i >= n4) break;
            float fs0 = fa[k].x + fa[k].y;
            float fs1 = fa[k].z + fa[k].w;
            float2 tx, ty;
            tx.x = (xa[k].x + xa[k].y) * invx + fs0;
            tx.y = (xa[k].z + xa[k].w) * invx + fs1;
            ty.x = (ya[k].x + ya[k].y) * invy + fs0;
            ty.y = (ya[k].z + ya[k].w) * invy + fs1;
            ((float2*)g_tx2)[i] = tx;
            ((float2*)g_ty2)[i] = ty;
        }
        base += 2 * stride;
    }
}

// ---------------------------------------------------------------------------
// Pass 3: gather. 8 rows per warp, loads front-batched for MLP=8/thread.
// Row layout: out row = [TX2[i0][0..63], TY2[i1][0..63]] = 32 float4.
// lanes 0-15 take the TX2 half, lanes 16-31 the TY2 half.
// Streaming stores (__stcs): output never re-read, keep tables L2-hot.
// ---------------------------------------------------------------------------
__global__ void __launch_bounds__(256)
gather_kernel(const int2* __restrict__ pos, float4* __restrict__ out,
              int nrows) {
    int warp = (blockIdx.x * blockDim.x + threadIdx.x) >> 5;
    int lane = threadIdx.x & 31;
    int base = warp * ROWS_PER_WARP;
    if (base >= nrows) return;

    const float4* tab = (lane < 16) ? (const float4*)g_tx2
                                    : (const float4*)g_ty2;
    int off = lane & 15;
    bool use_x = (lane < 16);

    int idx[ROWS_PER_WARP];
#pragma unroll
    for (int k = 0; k < ROWS_PER_WARP; k++) {
        int r = base + k;
        int2 p = (r < nrows) ? __ldg(&pos[r]) : make_int2(1, 1);
        int t = use_x ? p.x : p.y;
        idx[k] = (t < 0) ? 1 : t;
    }

    float4 v[ROWS_PER_WARP];
#pragma unroll
    for (int k = 0; k < ROWS_PER_WARP; k++) {
        v[k] = __ldg(tab + (size_t)idx[k] * 16 + off);
    }

#pragma unroll
    for (int k = 0; k < ROWS_PER_WARP; k++) {
        int r = base + k;
        if (r < nrows) __stcs(&out[(size_t)r * 32 + lane], v[k]);
    }
}

extern "C" void kernel_launch(void* const* d_in, const int* in_sizes, int n_in,
                              void* d_out, int out_size) {
    const int*   positions   = (const int*)d_in[0];   // [16,512,32,2] int32
    const float* fixed_table = (const float*)d_in[1]; // [table_len,128]
    const float* table_x     = (const float*)d_in[2];
    const float* table_y     = (const float*)d_in[3];

    int table_elems = in_sizes[1];        // table_len * 128
    int n4_tab      = table_elems / 4;    // float4 count per table
    int nrows       = in_sizes[0] / 2;    // 262144 output rows

    max_kernel<<<MAXB_MAX, 256>>>((const float4*)table_x,
                                  (const float4*)table_y, n4_tab);
    build_kernel<<<MAXB_BUILD, 256>>>((const float4*)table_x,
                                      (const float4*)table_y,
                                      (const float4*)fixed_table, n4_tab);
    {
        int threads = 256;  // 8 warps/block, 8 rows/warp
        int nwarps = (nrows + ROWS_PER_WARP - 1) / ROWS_PER_WARP;
        int blocks = (nwarps * 32 + threads - 1) / threads;
        gather_kernel<<<blocks, threads>>>((const int2*)positions,
                                           (float4*)d_out, nrows);
    }
}